// round 14
// baseline (speedup 1.0000x reference)
#include <cuda_runtime.h>
#include <cuda_fp16.h>
#include <cstdint>

// Problem dims
#define BDIM 65536
#define HDIM 1024
#define SDIM 1024
#define DDIM 128
#define LODIM 2048   // 2*SDIM : [read logits | write logits] per row

// ---------------- scratch (device globals: allocation-free rule) ----------------
__device__ __half g_logith[(size_t)BDIM * LODIM];  // fp16 logits (raw; softmax downstream)
__device__ float g_part[1024 * 1024];              // partial column sums
__device__ float g_cmean_h[HDIM];
__device__ float g_wmean[SDIM];
__device__ float g_cvec[DDIM];
__device__ float g_bias[LODIM];                    // [b_read | b_write]

__device__ __half g_qh[(size_t)BDIM * HDIM];   // query fp16       [B][H]
__device__ __half g_wt[(size_t)LODIM * HDIM];  // [Wr|Ww]^T fp16   [N=2048][K=1024]
__device__ __half g_mth[(size_t)DDIM * SDIM];  // memory^T hi limb [D=128][S=1024]
__device__ __half g_mtl[(size_t)DDIM * SDIM];  // memory^T lo limb
__device__ __half g_rwh[(size_t)BDIM * SDIM];  // read weights fp16 [B][S]

// ---------------- helpers ----------------
__device__ __forceinline__ uint32_t smem_u32(const void* p) {
    uint32_t a;
    asm("{ .reg .u64 t; cvta.to.shared.u64 t, %1; cvt.u32.u64 %0, t; }" : "=r"(a) : "l"(p));
    return a;
}
__device__ __forceinline__ void ldsm_x4(uint32_t* r, uint32_t addr) {
    asm volatile("ldmatrix.sync.aligned.m8n8.x4.shared.b16 {%0,%1,%2,%3}, [%4];"
                 : "=r"(r[0]), "=r"(r[1]), "=r"(r[2]), "=r"(r[3]) : "r"(addr));
}
__device__ __forceinline__ void mma16816(float* c, const uint32_t* a, const uint32_t* b) {
    asm volatile(
        "mma.sync.aligned.m16n8k16.row.col.f32.f16.f16.f32 "
        "{%0,%1,%2,%3}, {%4,%5,%6,%7}, {%8,%9}, {%0,%1,%2,%3};"
        : "+f"(c[0]), "+f"(c[1]), "+f"(c[2]), "+f"(c[3])
        : "r"(a[0]), "r"(a[1]), "r"(a[2]), "r"(a[3]), "r"(b[0]), "r"(b[1]));
}
__device__ __forceinline__ void cp16(uint32_t saddr, const void* g) {
    asm volatile("cp.async.cg.shared.global [%0], [%1], 16;" :: "r"(saddr), "l"(g));
}

__device__ __forceinline__ float warpMax(float v) {
    #pragma unroll
    for (int o = 16; o > 0; o >>= 1) v = fmaxf(v, __shfl_xor_sync(0xffffffffu, v, o));
    return v;
}
__device__ __forceinline__ float warpSum(float v) {
    #pragma unroll
    for (int o = 16; o > 0; o >>= 1) v += __shfl_xor_sync(0xffffffffu, v, o);
    return v;
}
// fp16 hi/lo split: x ~= h + l with residual ~2^-22 rel
__device__ __forceinline__ void split_f16(float x, __half& h, __half& l) {
    h = __float2half_rn(x);
    l = __float2half_rn(x - __half2float(h));
}

#define TILE_B 10240            // one 128x32 fp16 tile (stride 40 elems = 80B)
#define NSTAGE 3

// ============================================================================
// GEMM1: plain fp16 single-product. logith = fp16(q @ W^T + bias).
// CTA tile 128x128, BK=32, 3-stage cp.async (wait_group 1), one barrier/iter.
// smem 60KB, <=128 regs => 2 CTAs/SM.
// ============================================================================
#define G1_STAGE (2 * TILE_B)   // A | B
#define G1_SMEM (NSTAGE * G1_STAGE)

__global__ __launch_bounds__(256, 2) void gemm1_f16()
{
    extern __shared__ char sm[];
    const uint32_t sb = smem_u32(sm);
    const int tid = threadIdx.x, lane = tid & 31, wid = tid >> 5;
    const int wm = wid >> 2, wn = wid & 3;            // 2 x 4 warp grid
    const int m0 = blockIdx.y * 128, n0 = blockIdx.x * 128;

    float acc[4][4][4];
    #pragma unroll
    for (int i = 0; i < 4; ++i)
        #pragma unroll
        for (int j = 0; j < 4; ++j)
            #pragma unroll
            for (int k = 0; k < 4; ++k) acc[i][j][k] = 0.f;

    const int r_ld[2]  = { (tid + 0) >> 2, (tid + 256) >> 2 };
    const int c_ld[2]  = { (tid + 0) & 3,  (tid + 256) & 3 };

    auto load_stage = [&](int s, int k0) {
        const uint32_t base = sb + s * G1_STAGE;
        #pragma unroll
        for (int t = 0; t < 2; ++t) {
            const __half* g = t ? g_wt : g_qh;
            const int row0 = t ? n0 : m0;
            #pragma unroll
            for (int j = 0; j < 2; ++j) {
                const int r = r_ld[j], c = c_ld[j];
                cp16(base + t * TILE_B + r * 80 + c * 16,
                     g + (size_t)(row0 + r) * 1024 + k0 + c * 8);
            }
        }
        asm volatile("cp.async.commit_group;" ::: "memory");
    };

    const int lane8 = lane & 7, laneT = lane >> 3;
    const uint32_t aRow = 64 * wm + lane8 + 8 * (laneT & 1);
    const uint32_t aCol = 16 * (laneT >> 1);
    const uint32_t bRow = 32 * wn + lane8 + 8 * (laneT >> 1);
    const uint32_t bCol = 16 * (laneT & 1);

    load_stage(0, 0);
    load_stage(1, 32);

    for (int c = 0; c < 32; ++c) {
        if (c < 31) asm volatile("cp.async.wait_group 1;" ::: "memory");
        else        asm volatile("cp.async.wait_group 0;" ::: "memory");
        __syncthreads();
        if (c + 2 < 32) load_stage((c + 2) % NSTAGE, (c + 2) * 32);

        const uint32_t aB = sb + (c % NSTAGE) * G1_STAGE;
        const uint32_t bB = aB + TILE_B;

        #pragma unroll
        for (int kk = 0; kk < 2; ++kk) {
            const uint32_t kb = kk * 32;
            uint32_t fa[4][4];
            #pragma unroll
            for (int mt = 0; mt < 4; ++mt)
                ldsm_x4(fa[mt], aB + (aRow + 16 * mt) * 80 + aCol + kb);
            #pragma unroll
            for (int np = 0; np < 2; ++np) {
                uint32_t fb[4];
                ldsm_x4(fb, bB + (bRow + 16 * np) * 80 + bCol + kb);
                #pragma unroll
                for (int mt = 0; mt < 4; ++mt)
                    #pragma unroll
                    for (int j = 0; j < 2; ++j)
                        mma16816(acc[mt][2 * np + j], fa[mt], &fb[j * 2]);
            }
        }
    }

    #pragma unroll
    for (int mt = 0; mt < 4; ++mt) {
        const int r0 = m0 + 64 * wm + 16 * mt + (lane >> 2);
        #pragma unroll
        for (int nt = 0; nt < 4; ++nt) {
            const int col = n0 + 32 * wn + 8 * nt + (lane & 3) * 2;
            const float b0 = g_bias[col], b1 = g_bias[col + 1];
            __half2 v0 = __floats2half2_rn(acc[mt][nt][0] + b0, acc[mt][nt][1] + b1);
            __half2 v1 = __floats2half2_rn(acc[mt][nt][2] + b0, acc[mt][nt][3] + b1);
            *reinterpret_cast<__half2*>(&g_logith[(size_t)r0 * LODIM + col]) = v0;
            *reinterpret_cast<__half2*>(&g_logith[(size_t)(r0 + 8) * LODIM + col]) = v1;
        }
    }
}

// ============================================================================
// GEMM2: fp16 2-product (A@Bh + A@Bl). read_content = weights @ memory.
// A = fp16 read weights; B = memory^T split hi/lo. 3-stage (wait_group 1).
// CTA tile 128x128, 90KB smem, 2 CTAs/SM.
// ============================================================================
#define G2_STAGE (3 * TILE_B)   // A | Bh | Bl
#define G2_SMEM (NSTAGE * G2_STAGE)

__global__ __launch_bounds__(256, 2) void gemm2_f16x2(float* __restrict__ Cout)
{
    extern __shared__ char sm[];
    const uint32_t sb = smem_u32(sm);
    const int tid = threadIdx.x, lane = tid & 31, wid = tid >> 5;
    const int wm = wid >> 2, wn = wid & 3;
    const int m0 = blockIdx.y * 128;

    float acc[4][4][4];
    #pragma unroll
    for (int i = 0; i < 4; ++i)
        #pragma unroll
        for (int j = 0; j < 4; ++j)
            #pragma unroll
            for (int k = 0; k < 4; ++k) acc[i][j][k] = 0.f;

    const int r_ld[2]  = { (tid + 0) >> 2, (tid + 256) >> 2 };
    const int c_ld[2]  = { (tid + 0) & 3,  (tid + 256) & 3 };

    auto load_stage = [&](int s, int k0) {
        const uint32_t base = sb + s * G2_STAGE;
        const __half* srcs[3] = { g_rwh, g_mth, g_mtl };
        #pragma unroll
        for (int t = 0; t < 3; ++t) {
            const __half* g = srcs[t];
            const int row0 = (t < 1) ? m0 : 0;
            #pragma unroll
            for (int j = 0; j < 2; ++j) {
                const int r = r_ld[j], c = c_ld[j];
                cp16(base + t * TILE_B + r * 80 + c * 16,
                     g + (size_t)(row0 + r) * 1024 + k0 + c * 8);
            }
        }
        asm volatile("cp.async.commit_group;" ::: "memory");
    };

    const int lane8 = lane & 7, laneT = lane >> 3;
    const uint32_t aRow = 64 * wm + lane8 + 8 * (laneT & 1);
    const uint32_t aCol = 16 * (laneT >> 1);
    const uint32_t bRow = 32 * wn + lane8 + 8 * (laneT >> 1);
    const uint32_t bCol = 16 * (laneT & 1);

    load_stage(0, 0);
    load_stage(1, 32);

    for (int c = 0; c < 32; ++c) {
        if (c < 31) asm volatile("cp.async.wait_group 1;" ::: "memory");
        else        asm volatile("cp.async.wait_group 0;" ::: "memory");
        __syncthreads();
        if (c + 2 < 32) load_stage((c + 2) % NSTAGE, (c + 2) * 32);

        const uint32_t aB = sb + (c % NSTAGE) * G2_STAGE;
        const uint32_t bH = aB + TILE_B;
        const uint32_t bL = aB + 2 * TILE_B;

        #pragma unroll
        for (int kk = 0; kk < 2; ++kk) {
            const uint32_t kb = kk * 32;
            uint32_t fa[4][4];
            #pragma unroll
            for (int mt = 0; mt < 4; ++mt)
                ldsm_x4(fa[mt], aB + (aRow + 16 * mt) * 80 + aCol + kb);
            #pragma unroll
            for (int np = 0; np < 2; ++np) {
                uint32_t fbh[4], fbl[4];
                const uint32_t ro = (bRow + 16 * np) * 80 + bCol + kb;
                ldsm_x4(fbh, bH + ro);
                ldsm_x4(fbl, bL + ro);
                #pragma unroll
                for (int mt = 0; mt < 4; ++mt)
                    #pragma unroll
                    for (int j = 0; j < 2; ++j) {
                        const int nt = 2 * np + j;
                        mma16816(acc[mt][nt], fa[mt], &fbh[j * 2]);
                        mma16816(acc[mt][nt], fa[mt], &fbl[j * 2]);
                    }
            }
        }
    }

    #pragma unroll
    for (int mt = 0; mt < 4; ++mt) {
        const int r0 = m0 + 64 * wm + 16 * mt + (lane >> 2);
        #pragma unroll
        for (int nt = 0; nt < 4; ++nt) {
            const int col = 32 * wn + 8 * nt + (lane & 3) * 2;
            float2 v0 = make_float2(acc[mt][nt][0], acc[mt][nt][1]);
            float2 v1 = make_float2(acc[mt][nt][2], acc[mt][nt][3]);
            *reinterpret_cast<float2*>(&Cout[(size_t)r0 * DDIM + col]) = v0;
            *reinterpret_cast<float2*>(&Cout[(size_t)(r0 + 8) * DDIM + col]) = v1;
        }
    }
}

// ============================================================================
// fused prologue: one launch covering all conversions + bias prep.
// blocks [0,65536): convert_q; [65536,67584): convert_w transpose tiles;
// [67584,68096): convert_mem; [68096,68104): prep_bias.
// ============================================================================
#define PRO_Q 65536
#define PRO_W (PRO_Q + 2048)
#define PRO_M (PRO_W + 512)
#define PRO_END (PRO_M + 8)

__global__ __launch_bounds__(256) void prologue(
    const float* __restrict__ q,
    const float* __restrict__ Wr, const float* __restrict__ Ww,
    const float* __restrict__ mem,
    const float* __restrict__ br, const float* __restrict__ bw)
{
    __shared__ float tile[32][33];
    const int b = blockIdx.x;

    if (b < PRO_Q) {
        size_t i = (size_t)b * 256 + threadIdx.x;   // float4 index
        float4 v = reinterpret_cast<const float4*>(q)[i];
        *reinterpret_cast<ushort4*>(g_qh + i * 4) =
            make_ushort4(__half_as_ushort(__float2half_rn(v.x)),
                         __half_as_ushort(__float2half_rn(v.y)),
                         __half_as_ushort(__float2half_rn(v.z)),
                         __half_as_ushort(__float2half_rn(v.w)));
    } else if (b < PRO_W) {
        const int bb = b - PRO_Q;
        const int tx = threadIdx.x & 31, ty = threadIdx.x >> 5;   // 32 x 8
        const int ntile = (bb & 63) * 32;                 // n in [0,2048)
        const int ktile = (bb >> 6) * 32;                 // k in [0,1024)
        const float* Wm = (ntile < SDIM) ? Wr : Ww;
        const int nloc = (ntile < SDIM) ? ntile : ntile - SDIM;
        #pragma unroll
        for (int j = 0; j < 4; ++j)
            tile[ty + 8 * j][tx] = Wm[(size_t)(ktile + ty + 8 * j) * SDIM + nloc + tx];
        __syncthreads();
        #pragma unroll
        for (int j = 0; j < 4; ++j)
            g_wt[(size_t)(ntile + ty + 8 * j) * HDIM + ktile + tx] =
                __float2half_rn(tile[tx][ty + 8 * j]);
    } else if (b < PRO_M) {
        size_t id = (size_t)(b - PRO_W) * 256 + threadIdx.x;   // 128*1024
        int d = (int)(id >> 10), s = (int)(id & 1023);
        __half h, l; split_f16(mem[(size_t)s * DDIM + d], h, l);
        g_mth[id] = h; g_mtl[id] = l;
    } else {
        int i = (b - PRO_M) * 256 + threadIdx.x;
        g_bias[i] = (i < SDIM) ? br[i] : bw[i - SDIM];
    }
}

// ============================================================================
// warp-per-row fused softmax (fp16 logits in, no block barriers in hot loop)
// ============================================================================
__global__ __launch_bounds__(256) void softmax_fused() {
    __shared__ float sred[8][1024];
    const int lane = threadIdx.x & 31, wid = threadIdx.x >> 5;

    float part[32];
    #pragma unroll
    for (int i = 0; i < 32; ++i) part[i] = 0.f;

    for (int r = 0; r < 8; ++r) {
        const size_t row = (size_t)blockIdx.x * 64 + wid * 8 + r;
        const __half* lg = g_logith + row * LODIM;

        #pragma unroll
        for (int half = 0; half < 2; ++half) {
            float v[32];
            float m = -1e30f;
            #pragma unroll
            for (int i = 0; i < 8; ++i) {
                uint2 p = *reinterpret_cast<const uint2*>(lg + half * SDIM + 128 * i + 4 * lane);
                float2 f0 = __half22float2(*reinterpret_cast<__half2*>(&p.x));
                float2 f1 = __half22float2(*reinterpret_cast<__half2*>(&p.y));
                v[4 * i] = f0.x; v[4 * i + 1] = f0.y;
                v[4 * i + 2] = f1.x; v[4 * i + 3] = f1.y;
                m = fmaxf(m, fmaxf(fmaxf(f0.x, f0.y), fmaxf(f1.x, f1.y)));
            }
            m = warpMax(m);
            float s = 0.f;
            #pragma unroll
            for (int i = 0; i < 32; ++i) { v[i] = __expf(v[i] - m); s += v[i]; }
            s = warpSum(s);
            const float inv = 1.0f / s;

            if (half == 0) {
                __half* wh = g_rwh + row * SDIM;
                #pragma unroll
                for (int i = 0; i < 8; ++i) {
                    __half2 a = __floats2half2_rn(v[4 * i] * inv, v[4 * i + 1] * inv);
                    __half2 b = __floats2half2_rn(v[4 * i + 2] * inv, v[4 * i + 3] * inv);
                    uint2 ph;
                    ph.x = *reinterpret_cast<uint32_t*>(&a);
                    ph.y = *reinterpret_cast<uint32_t*>(&b);
                    *reinterpret_cast<uint2*>(wh + 128 * i + 4 * lane) = ph;
                }
            } else {
                #pragma unroll
                for (int i = 0; i < 32; ++i) part[i] += v[i] * inv;
            }
        }
    }

    #pragma unroll
    for (int i = 0; i < 8; ++i)
        #pragma unroll
        for (int j = 0; j < 4; ++j)
            sred[wid][128 * i + 4 * lane + j] = part[4 * i + j];
    __syncthreads();
    const int t = threadIdx.x;
    #pragma unroll
    for (int cb = 0; cb < 4; ++cb) {
        const int c = t + 256 * cb;
        float s = 0.f;
        #pragma unroll
        for (int w = 0; w < 8; ++w) s += sred[w][c];
        g_part[(size_t)blockIdx.x * 1024 + c] = s;
    }
}

// ============================================================================
// deterministic two-stage column sums
// ============================================================================
__global__ __launch_bounds__(256) void colsum_stage1(
    const float* __restrict__ X, int ld) {
    const int p = blockIdx.x, t = threadIdx.x;
    float a0 = 0.f, a1 = 0.f, a2 = 0.f, a3 = 0.f;
    const float* base = X + (size_t)p * 256 * ld;
    for (int r = 0; r < 256; ++r) {
        const float* row = base + (size_t)r * ld;
        a0 += row[t]; a1 += row[t + 256]; a2 += row[t + 512]; a3 += row[t + 768];
    }
    float* o = g_part + p * 1024;
    o[t] = a0; o[t + 256] = a1; o[t + 512] = a2; o[t + 768] = a3;
}

__global__ __launch_bounds__(256) void colsum_stage2(int dst, float scale, int nparts) {
    const int c = blockIdx.x * 256 + threadIdx.x;
    float s = 0.f;
    for (int p = 0; p < nparts; ++p) s += g_part[p * 1024 + c];
    s *= scale;
    if (dst == 0) g_cmean_h[c] = s; else g_wmean[c] = s;
}

__global__ void project_cmean_kernel(const float* __restrict__ Wc,
                                     const float* __restrict__ bc) {
    const int d = threadIdx.x;   // 128 threads
    float s = bc[d];
    #pragma unroll 4
    for (int h = 0; h < HDIM; ++h) s += g_cmean_h[h] * Wc[h * DDIM + d];
    g_cvec[d] = s;
}

__global__ void update_kernel(const float* __restrict__ memory,
                              const float* __restrict__ age,
                              float* __restrict__ out_mem,
                              float* __restrict__ out_age) {
    const int s = blockIdx.x;
    const int d = threadIdx.x;
    const float wm = g_wmean[s];
    const float a  = age[s];
    const bool mask = wm > 0.01f;
    const float cons = 1.0f / (1.0f + __expf(-a * 0.1f));
    const float f = mask ? wm * cons : 0.0f;
    const float m = memory[s * DDIM + d];
    out_mem[s * DDIM + d] = (1.0f - f) * m + f * g_cvec[d];
    if (d == 0) out_age[s] = a + (mask ? 1.0f : 0.0f);
}

// ============================================================================
extern "C" void kernel_launch(void* const* d_in, const int* in_sizes, int n_in,
                              void* d_out, int out_size) {
    const float* query   = (const float*)d_in[0];
    const float* content = (const float*)d_in[1];
    const float* memory  = (const float*)d_in[2];
    const float* age     = (const float*)d_in[3];
    const float* W_read  = (const float*)d_in[4];
    const float* b_read  = (const float*)d_in[5];
    const float* W_write = (const float*)d_in[6];
    const float* b_write = (const float*)d_in[7];
    const float* W_cont  = (const float*)d_in[8];
    const float* b_cont  = (const float*)d_in[9];

    float* out      = (float*)d_out;
    float* out_read = out;                                   // [B, D]
    float* out_mem  = out + (size_t)BDIM * DDIM;             // [S, D]
    float* out_age  = out_mem + (size_t)SDIM * DDIM;         // [S]

    cudaFuncSetAttribute(gemm1_f16, cudaFuncAttributeMaxDynamicSharedMemorySize, G1_SMEM);
    cudaFuncSetAttribute(gemm2_f16x2, cudaFuncAttributeMaxDynamicSharedMemorySize, G2_SMEM);

    // fused conversions + bias prep (one launch)
    prologue<<<PRO_END, 256>>>(query, W_read, W_write, memory, b_read, b_write);

    // content mean -> c_vec (mean before projection: algebraically identical)
    colsum_stage1<<<256, 256>>>(content, HDIM);
    colsum_stage2<<<4, 256>>>(0, 1.0f / (float)BDIM, 256);
    project_cmean_kernel<<<1, 128>>>(W_cont, b_cont);

    // GEMM1: logith = fp16(Q @ [Wr|Ww] + bias)
    gemm1_f16<<<dim3(16, BDIM / 128), 256, G1_SMEM>>>();

    // warp-per-row fused softmax + write-weight partial column sums
    softmax_fused<<<1024, 256>>>();
    colsum_stage2<<<4, 256>>>(1, 1.0f / (float)BDIM, 1024);

    // GEMM2: read_content = read_weights @ memory (fp16 2-product, B hi/lo)
    gemm2_f16x2<<<dim3(1, BDIM / 128), 256, G2_SMEM>>>(out_read);

    // memory + age update
    update_kernel<<<SDIM, DDIM>>>(memory, age, out_mem, out_age);
}

// round 15
// speedup vs baseline: 1.1074x; 1.1074x over previous
#include <cuda_runtime.h>
#include <cuda_fp16.h>
#include <cstdint>

// Problem dims
#define BDIM 65536
#define HDIM 1024
#define SDIM 1024
#define DDIM 128
#define LODIM 2048   // 2*SDIM : [read logits | write logits] per row

// ---------------- scratch (device globals: allocation-free rule) ----------------
__device__ __half g_logith[(size_t)BDIM * LODIM];  // fp16 logits (raw; softmax downstream)
__device__ float g_part[1024 * 1024];              // partial column sums
__device__ float g_cmean_h[HDIM];
__device__ float g_wmean[SDIM];
__device__ float g_cvec[DDIM];
__device__ float g_bias[LODIM];                    // [b_read | b_write]

__device__ __half g_qh[(size_t)BDIM * HDIM];   // query fp16       [B][H]
__device__ __half g_wt[(size_t)LODIM * HDIM];  // [Wr|Ww]^T fp16   [N=2048][K=1024]
__device__ __half g_mth[(size_t)DDIM * SDIM];  // memory^T hi limb [D=128][S=1024]
__device__ __half g_mtl[(size_t)DDIM * SDIM];  // memory^T lo limb
__device__ __half g_rwh[(size_t)BDIM * SDIM];  // read weights fp16 [B][S]

// ---------------- helpers ----------------
__device__ __forceinline__ uint32_t smem_u32(const void* p) {
    uint32_t a;
    asm("{ .reg .u64 t; cvta.to.shared.u64 t, %1; cvt.u32.u64 %0, t; }" : "=r"(a) : "l"(p));
    return a;
}
__device__ __forceinline__ void ldsm_x4(uint32_t* r, uint32_t addr) {
    asm volatile("ldmatrix.sync.aligned.m8n8.x4.shared.b16 {%0,%1,%2,%3}, [%4];"
                 : "=r"(r[0]), "=r"(r[1]), "=r"(r[2]), "=r"(r[3]) : "r"(addr));
}
__device__ __forceinline__ void mma16816(float* c, const uint32_t* a, const uint32_t* b) {
    asm volatile(
        "mma.sync.aligned.m16n8k16.row.col.f32.f16.f16.f32 "
        "{%0,%1,%2,%3}, {%4,%5,%6,%7}, {%8,%9}, {%0,%1,%2,%3};"
        : "+f"(c[0]), "+f"(c[1]), "+f"(c[2]), "+f"(c[3])
        : "r"(a[0]), "r"(a[1]), "r"(a[2]), "r"(a[3]), "r"(b[0]), "r"(b[1]));
}
__device__ __forceinline__ void cp16(uint32_t saddr, const void* g) {
    asm volatile("cp.async.cg.shared.global [%0], [%1], 16;" :: "r"(saddr), "l"(g));
}

__device__ __forceinline__ float warpMax(float v) {
    #pragma unroll
    for (int o = 16; o > 0; o >>= 1) v = fmaxf(v, __shfl_xor_sync(0xffffffffu, v, o));
    return v;
}
__device__ __forceinline__ float warpSum(float v) {
    #pragma unroll
    for (int o = 16; o > 0; o >>= 1) v += __shfl_xor_sync(0xffffffffu, v, o);
    return v;
}
// fp16 hi/lo split: x ~= h + l with residual ~2^-22 rel
__device__ __forceinline__ void split_f16(float x, __half& h, __half& l) {
    h = __float2half_rn(x);
    l = __float2half_rn(x - __half2float(h));
}

#define TILE_B 10240            // one 128x32 fp16 tile (stride 40 elems = 80B)

// ============================================================================
// GEMM1: plain fp16 single-product. logith = fp16(q @ W^T + bias).
// CTA tile 128x128, BK=32, 2-stage cp.async, one barrier per k-iter.
// smem 40KB, <=128 regs => 2 CTAs/SM.  (R12-exact, best-known config.)
// ============================================================================
#define G1_STAGE (2 * TILE_B)   // A | B
#define G1_SMEM (2 * G1_STAGE)

__global__ __launch_bounds__(256, 2) void gemm1_f16()
{
    extern __shared__ char sm[];
    const uint32_t sb = smem_u32(sm);
    const int tid = threadIdx.x, lane = tid & 31, wid = tid >> 5;
    const int wm = wid >> 2, wn = wid & 3;            // 2 x 4 warp grid
    const int m0 = blockIdx.y * 128, n0 = blockIdx.x * 128;

    float acc[4][4][4];
    #pragma unroll
    for (int i = 0; i < 4; ++i)
        #pragma unroll
        for (int j = 0; j < 4; ++j)
            #pragma unroll
            for (int k = 0; k < 4; ++k) acc[i][j][k] = 0.f;

    const int r_ld[2]  = { (tid + 0) >> 2, (tid + 256) >> 2 };
    const int c_ld[2]  = { (tid + 0) & 3,  (tid + 256) & 3 };

    auto load_stage = [&](int s, int k0) {
        const uint32_t base = sb + s * G1_STAGE;
        #pragma unroll
        for (int t = 0; t < 2; ++t) {
            const __half* g = t ? g_wt : g_qh;
            const int row0 = t ? n0 : m0;
            #pragma unroll
            for (int j = 0; j < 2; ++j) {
                const int r = r_ld[j], c = c_ld[j];
                cp16(base + t * TILE_B + r * 80 + c * 16,
                     g + (size_t)(row0 + r) * 1024 + k0 + c * 8);
            }
        }
        asm volatile("cp.async.commit_group;" ::: "memory");
    };

    const int lane8 = lane & 7, laneT = lane >> 3;
    const uint32_t aRow = 64 * wm + lane8 + 8 * (laneT & 1);
    const uint32_t aCol = 16 * (laneT >> 1);
    const uint32_t bRow = 32 * wn + lane8 + 8 * (laneT >> 1);
    const uint32_t bCol = 16 * (laneT & 1);

    load_stage(0, 0);

    for (int c = 0; c < 32; ++c) {
        asm volatile("cp.async.wait_group 0;" ::: "memory");
        __syncthreads();
        if (c + 1 < 32) load_stage((c + 1) & 1, (c + 1) * 32);

        const uint32_t aB = sb + (c & 1) * G1_STAGE;
        const uint32_t bB = aB + TILE_B;

        #pragma unroll
        for (int kk = 0; kk < 2; ++kk) {
            const uint32_t kb = kk * 32;
            uint32_t fa[4][4];
            #pragma unroll
            for (int mt = 0; mt < 4; ++mt)
                ldsm_x4(fa[mt], aB + (aRow + 16 * mt) * 80 + aCol + kb);
            #pragma unroll
            for (int np = 0; np < 2; ++np) {
                uint32_t fb[4];
                ldsm_x4(fb, bB + (bRow + 16 * np) * 80 + bCol + kb);
                #pragma unroll
                for (int mt = 0; mt < 4; ++mt)
                    #pragma unroll
                    for (int j = 0; j < 2; ++j)
                        mma16816(acc[mt][2 * np + j], fa[mt], &fb[j * 2]);
            }
        }
    }

    #pragma unroll
    for (int mt = 0; mt < 4; ++mt) {
        const int r0 = m0 + 64 * wm + 16 * mt + (lane >> 2);
        #pragma unroll
        for (int nt = 0; nt < 4; ++nt) {
            const int col = n0 + 32 * wn + 8 * nt + (lane & 3) * 2;
            const float b0 = g_bias[col], b1 = g_bias[col + 1];
            __half2 v0 = __floats2half2_rn(acc[mt][nt][0] + b0, acc[mt][nt][1] + b1);
            __half2 v1 = __floats2half2_rn(acc[mt][nt][2] + b0, acc[mt][nt][3] + b1);
            *reinterpret_cast<__half2*>(&g_logith[(size_t)r0 * LODIM + col]) = v0;
            *reinterpret_cast<__half2*>(&g_logith[(size_t)(r0 + 8) * LODIM + col]) = v1;
        }
    }
}

// ============================================================================
// GEMM2: fp16 2-product (A@Bh + A@Bl). read_content = weights @ memory.
// A = fp16 read weights; B = memory^T split hi/lo. 2-stage, 60KB smem.
// (R12-exact, best-known config.)
// ============================================================================
#define G2_STAGE (3 * TILE_B)   // A | Bh | Bl
#define G2_SMEM (2 * G2_STAGE)

__global__ __launch_bounds__(256, 2) void gemm2_f16x2(float* __restrict__ Cout)
{
    extern __shared__ char sm[];
    const uint32_t sb = smem_u32(sm);
    const int tid = threadIdx.x, lane = tid & 31, wid = tid >> 5;
    const int wm = wid >> 2, wn = wid & 3;
    const int m0 = blockIdx.y * 128;

    float acc[4][4][4];
    #pragma unroll
    for (int i = 0; i < 4; ++i)
        #pragma unroll
        for (int j = 0; j < 4; ++j)
            #pragma unroll
            for (int k = 0; k < 4; ++k) acc[i][j][k] = 0.f;

    const int r_ld[2]  = { (tid + 0) >> 2, (tid + 256) >> 2 };
    const int c_ld[2]  = { (tid + 0) & 3,  (tid + 256) & 3 };

    auto load_stage = [&](int s, int k0) {
        const uint32_t base = sb + s * G2_STAGE;
        const __half* srcs[3] = { g_rwh, g_mth, g_mtl };
        #pragma unroll
        for (int t = 0; t < 3; ++t) {
            const __half* g = srcs[t];
            const int row0 = (t < 1) ? m0 : 0;
            #pragma unroll
            for (int j = 0; j < 2; ++j) {
                const int r = r_ld[j], c = c_ld[j];
                cp16(base + t * TILE_B + r * 80 + c * 16,
                     g + (size_t)(row0 + r) * 1024 + k0 + c * 8);
            }
        }
        asm volatile("cp.async.commit_group;" ::: "memory");
    };

    const int lane8 = lane & 7, laneT = lane >> 3;
    const uint32_t aRow = 64 * wm + lane8 + 8 * (laneT & 1);
    const uint32_t aCol = 16 * (laneT >> 1);
    const uint32_t bRow = 32 * wn + lane8 + 8 * (laneT >> 1);
    const uint32_t bCol = 16 * (laneT & 1);

    load_stage(0, 0);

    for (int c = 0; c < 32; ++c) {
        asm volatile("cp.async.wait_group 0;" ::: "memory");
        __syncthreads();
        if (c + 1 < 32) load_stage((c + 1) & 1, (c + 1) * 32);

        const uint32_t aB = sb + (c & 1) * G2_STAGE;
        const uint32_t bH = aB + TILE_B;
        const uint32_t bL = aB + 2 * TILE_B;

        #pragma unroll
        for (int kk = 0; kk < 2; ++kk) {
            const uint32_t kb = kk * 32;
            uint32_t fa[4][4];
            #pragma unroll
            for (int mt = 0; mt < 4; ++mt)
                ldsm_x4(fa[mt], aB + (aRow + 16 * mt) * 80 + aCol + kb);
            #pragma unroll
            for (int np = 0; np < 2; ++np) {
                uint32_t fbh[4], fbl[4];
                const uint32_t ro = (bRow + 16 * np) * 80 + bCol + kb;
                ldsm_x4(fbh, bH + ro);
                ldsm_x4(fbl, bL + ro);
                #pragma unroll
                for (int mt = 0; mt < 4; ++mt)
                    #pragma unroll
                    for (int j = 0; j < 2; ++j) {
                        const int nt = 2 * np + j;
                        mma16816(acc[mt][nt], fa[mt], &fbh[j * 2]);
                        mma16816(acc[mt][nt], fa[mt], &fbl[j * 2]);
                    }
            }
        }
    }

    #pragma unroll
    for (int mt = 0; mt < 4; ++mt) {
        const int r0 = m0 + 64 * wm + 16 * mt + (lane >> 2);
        #pragma unroll
        for (int nt = 0; nt < 4; ++nt) {
            const int col = 32 * wn + 8 * nt + (lane & 3) * 2;
            float2 v0 = make_float2(acc[mt][nt][0], acc[mt][nt][1]);
            float2 v1 = make_float2(acc[mt][nt][2], acc[mt][nt][3]);
            *reinterpret_cast<float2*>(&Cout[(size_t)r0 * DDIM + col]) = v0;
            *reinterpret_cast<float2*>(&Cout[(size_t)(r0 + 8) * DDIM + col]) = v1;
        }
    }
}

// ============================================================================
// fused prologue: one launch covering all conversions + bias prep.
// ============================================================================
#define PRO_Q 65536
#define PRO_W (PRO_Q + 2048)
#define PRO_M (PRO_W + 512)
#define PRO_END (PRO_M + 8)

__global__ __launch_bounds__(256) void prologue(
    const float* __restrict__ q,
    const float* __restrict__ Wr, const float* __restrict__ Ww,
    const float* __restrict__ mem,
    const float* __restrict__ br, const float* __restrict__ bw)
{
    __shared__ float tile[32][33];
    const int b = blockIdx.x;

    if (b < PRO_Q) {
        size_t i = (size_t)b * 256 + threadIdx.x;   // float4 index
        float4 v = reinterpret_cast<const float4*>(q)[i];
        *reinterpret_cast<ushort4*>(g_qh + i * 4) =
            make_ushort4(__half_as_ushort(__float2half_rn(v.x)),
                         __half_as_ushort(__float2half_rn(v.y)),
                         __half_as_ushort(__float2half_rn(v.z)),
                         __half_as_ushort(__float2half_rn(v.w)));
    } else if (b < PRO_W) {
        const int bb = b - PRO_Q;
        const int tx = threadIdx.x & 31, ty = threadIdx.x >> 5;   // 32 x 8
        const int ntile = (bb & 63) * 32;                 // n in [0,2048)
        const int ktile = (bb >> 6) * 32;                 // k in [0,1024)
        const float* Wm = (ntile < SDIM) ? Wr : Ww;
        const int nloc = (ntile < SDIM) ? ntile : ntile - SDIM;
        #pragma unroll
        for (int j = 0; j < 4; ++j)
            tile[ty + 8 * j][tx] = Wm[(size_t)(ktile + ty + 8 * j) * SDIM + nloc + tx];
        __syncthreads();
        #pragma unroll
        for (int j = 0; j < 4; ++j)
            g_wt[(size_t)(ntile + ty + 8 * j) * HDIM + ktile + tx] =
                __float2half_rn(tile[tx][ty + 8 * j]);
    } else if (b < PRO_M) {
        size_t id = (size_t)(b - PRO_W) * 256 + threadIdx.x;   // 128*1024
        int d = (int)(id >> 10), s = (int)(id & 1023);
        __half h, l; split_f16(mem[(size_t)s * DDIM + d], h, l);
        g_mth[id] = h; g_mtl[id] = l;
    } else {
        int i = (b - PRO_M) * 256 + threadIdx.x;
        g_bias[i] = (i < SDIM) ? br[i] : bw[i - SDIM];
    }
}

// ============================================================================
// warp-per-row fused softmax (fp16 logits in, no block barriers in hot loop)
// ============================================================================
__global__ __launch_bounds__(256) void softmax_fused() {
    __shared__ float sred[8][1024];
    const int lane = threadIdx.x & 31, wid = threadIdx.x >> 5;

    float part[32];
    #pragma unroll
    for (int i = 0; i < 32; ++i) part[i] = 0.f;

    for (int r = 0; r < 8; ++r) {
        const size_t row = (size_t)blockIdx.x * 64 + wid * 8 + r;
        const __half* lg = g_logith + row * LODIM;

        #pragma unroll
        for (int half = 0; half < 2; ++half) {
            float v[32];
            float m = -1e30f;
            #pragma unroll
            for (int i = 0; i < 8; ++i) {
                uint2 p = *reinterpret_cast<const uint2*>(lg + half * SDIM + 128 * i + 4 * lane);
                float2 f0 = __half22float2(*reinterpret_cast<__half2*>(&p.x));
                float2 f1 = __half22float2(*reinterpret_cast<__half2*>(&p.y));
                v[4 * i] = f0.x; v[4 * i + 1] = f0.y;
                v[4 * i + 2] = f1.x; v[4 * i + 3] = f1.y;
                m = fmaxf(m, fmaxf(fmaxf(f0.x, f0.y), fmaxf(f1.x, f1.y)));
            }
            m = warpMax(m);
            float s = 0.f;
            #pragma unroll
            for (int i = 0; i < 32; ++i) { v[i] = __expf(v[i] - m); s += v[i]; }
            s = warpSum(s);
            const float inv = 1.0f / s;

            if (half == 0) {
                __half* wh = g_rwh + row * SDIM;
                #pragma unroll
                for (int i = 0; i < 8; ++i) {
                    __half2 a = __floats2half2_rn(v[4 * i] * inv, v[4 * i + 1] * inv);
                    __half2 b = __floats2half2_rn(v[4 * i + 2] * inv, v[4 * i + 3] * inv);
                    uint2 ph;
                    ph.x = *reinterpret_cast<uint32_t*>(&a);
                    ph.y = *reinterpret_cast<uint32_t*>(&b);
                    *reinterpret_cast<uint2*>(wh + 128 * i + 4 * lane) = ph;
                }
            } else {
                #pragma unroll
                for (int i = 0; i < 32; ++i) part[i] += v[i] * inv;
            }
        }
    }

    #pragma unroll
    for (int i = 0; i < 8; ++i)
        #pragma unroll
        for (int j = 0; j < 4; ++j)
            sred[wid][128 * i + 4 * lane + j] = part[4 * i + j];
    __syncthreads();
    const int t = threadIdx.x;
    #pragma unroll
    for (int cb = 0; cb < 4; ++cb) {
        const int c = t + 256 * cb;
        float s = 0.f;
        #pragma unroll
        for (int w = 0; w < 8; ++w) s += sred[w][c];
        g_part[(size_t)blockIdx.x * 1024 + c] = s;
    }
}

// ============================================================================
// deterministic two-stage column sums
// ============================================================================
__global__ __launch_bounds__(256) void colsum_stage1(
    const float* __restrict__ X, int ld) {
    const int p = blockIdx.x, t = threadIdx.x;
    float a0 = 0.f, a1 = 0.f, a2 = 0.f, a3 = 0.f;
    const float* base = X + (size_t)p * 256 * ld;
    for (int r = 0; r < 256; ++r) {
        const float* row = base + (size_t)r * ld;
        a0 += row[t]; a1 += row[t + 256]; a2 += row[t + 512]; a3 += row[t + 768];
    }
    float* o = g_part + p * 1024;
    o[t] = a0; o[t + 256] = a1; o[t + 512] = a2; o[t + 768] = a3;
}

__global__ __launch_bounds__(256) void colsum_stage2(int dst, float scale, int nparts) {
    const int c = blockIdx.x * 256 + threadIdx.x;
    float s = 0.f;
    for (int p = 0; p < nparts; ++p) s += g_part[p * 1024 + c];
    s *= scale;
    if (dst == 0) g_cmean_h[c] = s; else g_wmean[c] = s;
}

// ============================================================================
// parallel c_vec projection: one block per output d (128 blocks, 256 thr).
// Deterministic: fixed per-thread order (4 h each), tree reduction.
// Replaces the 124us single-block serial version.
// ============================================================================
__global__ __launch_bounds__(256) void project_cmean_kernel(
    const float* __restrict__ Wc, const float* __restrict__ bc)
{
    __shared__ float red[8];
    const int d = blockIdx.x;       // 0..127
    const int t = threadIdx.x;      // 256 threads, 4 h each
    float s = 0.f;
    #pragma unroll
    for (int j = 0; j < 4; ++j) {
        const int h = t * 4 + j;
        s += g_cmean_h[h] * Wc[(size_t)h * DDIM + d];
    }
    s = warpSum(s);
    if ((t & 31) == 0) red[t >> 5] = s;
    __syncthreads();
    if (t < 32) {
        float v = (t < 8) ? red[t] : 0.f;
        v = warpSum(v);
        if (t == 0) g_cvec[d] = v + bc[d];
    }
}

__global__ void update_kernel(const float* __restrict__ memory,
                              const float* __restrict__ age,
                              float* __restrict__ out_mem,
                              float* __restrict__ out_age) {
    const int s = blockIdx.x;
    const int d = threadIdx.x;
    const float wm = g_wmean[s];
    const float a  = age[s];
    const bool mask = wm > 0.01f;
    const float cons = 1.0f / (1.0f + __expf(-a * 0.1f));
    const float f = mask ? wm * cons : 0.0f;
    const float m = memory[s * DDIM + d];
    out_mem[s * DDIM + d] = (1.0f - f) * m + f * g_cvec[d];
    if (d == 0) out_age[s] = a + (mask ? 1.0f : 0.0f);
}

// ============================================================================
extern "C" void kernel_launch(void* const* d_in, const int* in_sizes, int n_in,
                              void* d_out, int out_size) {
    const float* query   = (const float*)d_in[0];
    const float* content = (const float*)d_in[1];
    const float* memory  = (const float*)d_in[2];
    const float* age     = (const float*)d_in[3];
    const float* W_read  = (const float*)d_in[4];
    const float* b_read  = (const float*)d_in[5];
    const float* W_write = (const float*)d_in[6];
    const float* b_write = (const float*)d_in[7];
    const float* W_cont  = (const float*)d_in[8];
    const float* b_cont  = (const float*)d_in[9];

    float* out      = (float*)d_out;
    float* out_read = out;                                   // [B, D]
    float* out_mem  = out + (size_t)BDIM * DDIM;             // [S, D]
    float* out_age  = out_mem + (size_t)SDIM * DDIM;         // [S]

    cudaFuncSetAttribute(gemm1_f16, cudaFuncAttributeMaxDynamicSharedMemorySize, G1_SMEM);
    cudaFuncSetAttribute(gemm2_f16x2, cudaFuncAttributeMaxDynamicSharedMemorySize, G2_SMEM);

    // fused conversions + bias prep (one launch)
    prologue<<<PRO_END, 256>>>(query, W_read, W_write, memory, b_read, b_write);

    // content mean -> c_vec (mean before projection: algebraically identical)
    colsum_stage1<<<256, 256>>>(content, HDIM);
    colsum_stage2<<<4, 256>>>(0, 1.0f / (float)BDIM, 256);
    project_cmean_kernel<<<DDIM, 256>>>(W_cont, b_cont);

    // GEMM1: logith = fp16(Q @ [Wr|Ww] + bias)
    gemm1_f16<<<dim3(16, BDIM / 128), 256, G1_SMEM>>>();

    // warp-per-row fused softmax + write-weight partial column sums
    softmax_fused<<<1024, 256>>>();
    colsum_stage2<<<4, 256>>>(1, 1.0f / (float)BDIM, 1024);

    // GEMM2: read_content = read_weights @ memory (fp16 2-product, B hi/lo)
    gemm2_f16x2<<<dim3(1, BDIM / 128), 256, G2_SMEM>>>(out_read);

    // memory + age update
    update_kernel<<<SDIM, DDIM>>>(memory, age, out_mem, out_age);
}